// round 1
// baseline (speedup 1.0000x reference)
#include <cuda_runtime.h>
#include <math.h>

// Problem constants (from reference)
#define N_MOL  2048
#define P_PRO  2048
#define HID    64
#define HEADS  16
#define NGRAPH 64

// Scratch (no cudaMalloc allowed)
__device__ float g_a_mol[N_MOL * HEADS];
__device__ float g_a_pro[P_PRO * HEADS];
__device__ float g_sorted[HEADS][P_PRO];
__device__ float g_prefExp[HEADS][P_PRO + 1];  // prefExp[h][k] = sum_{i<k} exp(sorted[h][i])
__device__ float g_sufSum[HEADS][P_PRO + 1];   // sufSum[h][k]  = sum_{i>=k} sorted[h][i]
__device__ float g_y_atom[N_MOL * HEADS];

// ---------------------------------------------------------------------------
// Kernel 1: projections  a_mol = mol @ Wmu[:HID] + bmu ;  a_pro = pro @ Wmu[HID:]
// 256 blocks x 256 threads; each thread computes one (row, head).
// ---------------------------------------------------------------------------
__global__ void proj_kernel(const float* __restrict__ mol,
                            const float* __restrict__ pro,
                            const float* __restrict__ Wmu,
                            const float* __restrict__ bmu) {
    __shared__ float Ws[2 * HID * HEADS];  // 2048 floats = 8KB
    int tid = threadIdx.x;
    for (int i = tid; i < 2 * HID * HEADS; i += blockDim.x) Ws[i] = Wmu[i];
    __syncthreads();

    int row = blockIdx.x * 16 + (tid >> 4);  // 0..4095
    int h   = tid & 15;

    const float* src;
    const float* w;
    float acc;
    bool is_mol = (row < N_MOL);
    if (is_mol) {
        src = mol + row * HID;
        w   = Ws;
        acc = bmu[h];
    } else {
        src = pro + (row - N_MOL) * HID;
        w   = Ws + HID * HEADS;
        acc = 0.0f;
    }
#pragma unroll
    for (int k = 0; k < HID; k++) acc += src[k] * w[k * HEADS + h];

    if (is_mol) g_a_mol[row * HEADS + h] = acc;
    else        g_a_pro[(row - N_MOL) * HEADS + h] = acc;
}

// ---------------------------------------------------------------------------
// Kernel 2: per-head bitonic sort of a_pro[:,h] + prefix(exp) and suffix(sum)
// scans in double precision. 16 blocks x 1024 threads.
// ---------------------------------------------------------------------------
__global__ void sort_scan_kernel() {
    __shared__ float  sv[P_PRO];     // 8KB
    __shared__ double dsc[1024];     // 8KB
    __shared__ double tot_sh;

    int h   = blockIdx.x;
    int tid = threadIdx.x;  // 0..1023

    sv[tid]        = g_a_pro[tid * HEADS + h];
    sv[tid + 1024] = g_a_pro[(tid + 1024) * HEADS + h];
    __syncthreads();

    // Bitonic sort (ascending)
    for (int k = 2; k <= P_PRO; k <<= 1) {
        for (int j = k >> 1; j > 0; j >>= 1) {
            for (int i = tid; i < P_PRO; i += 1024) {
                int ixj = i ^ j;
                if (ixj > i) {
                    float a = sv[i], b = sv[ixj];
                    bool up = ((i & k) == 0);
                    if ((a > b) == up) { sv[i] = b; sv[ixj] = a; }
                }
            }
            __syncthreads();
        }
    }

    g_sorted[h][tid]        = sv[tid];
    g_sorted[h][tid + 1024] = sv[tid + 1024];

    float v0 = sv[2 * tid];
    float v1 = sv[2 * tid + 1];

    // ---- scan 1: prefix sums of exp(sorted) ----
    double e0 = exp((double)v0);
    double e1 = exp((double)v1);
    double x  = e0 + e1;
    dsc[tid] = x;
    for (int off = 1; off < 1024; off <<= 1) {
        __syncthreads();
        double add = (tid >= off) ? dsc[tid - off] : 0.0;
        __syncthreads();
        dsc[tid] += add;
    }
    double incl = dsc[tid];
    double excl = incl - x;
    g_prefExp[h][2 * tid + 1] = (float)(excl + e0);
    g_prefExp[h][2 * tid + 2] = (float)incl;
    if (tid == 0) g_prefExp[h][0] = 0.0f;
    __syncthreads();

    // ---- scan 2: suffix sums of sorted values (stored directly: no cancellation) ----
    double xv = (double)v0 + (double)v1;
    dsc[tid] = xv;
    for (int off = 1; off < 1024; off <<= 1) {
        __syncthreads();
        double add = (tid >= off) ? dsc[tid - off] : 0.0;
        __syncthreads();
        dsc[tid] += add;
    }
    __syncthreads();
    if (tid == 1023) tot_sh = dsc[1023];
    __syncthreads();
    double total = tot_sh;
    double inclv = dsc[tid];
    double exclv = inclv - xv;
    g_sufSum[h][2 * tid + 1] = (float)(total - (exclv + (double)v0));
    g_sufSum[h][2 * tid + 2] = (float)(total - inclv);
    if (tid == 0) g_sufSum[h][0] = (float)total;
}

// ---------------------------------------------------------------------------
// Kernel 3: y_atom[n,h] via binary search into sorted a_pro. 32 blocks x 1024.
// ---------------------------------------------------------------------------
__global__ void ya_kernel() {
    int gid = blockIdx.x * blockDim.x + threadIdx.x;  // 0..32767
    int h   = gid & 15;

    float am = g_a_mol[gid];
    float t  = -am;

    // k = count of sorted[h][i] <= t  (exp branch: a_mol + a_pro <= 0)
    int lo = 0, hi = P_PRO;
    while (lo < hi) {
        int mid = (lo + hi) >> 1;
        if (g_sorted[h][mid] <= t) lo = mid + 1; else hi = mid;
    }

    float ya = expf(am) * g_prefExp[h][lo]
             + (float)(P_PRO - lo) * (am + 1.0f)
             + g_sufSum[h][lo];
    g_y_atom[gid] = ya;
}

// ---------------------------------------------------------------------------
// Kernel 4: segment-sum over mol_batch (sorted) + MLP head. 1 block x 1024.
// Handles mol_batch as int64 OR int32 (JAX without x64 silently downcasts).
// ---------------------------------------------------------------------------
__global__ void final_kernel(const void* __restrict__ batch_raw,
                             const float* __restrict__ W1,
                             const float* __restrict__ b1,
                             const float* __restrict__ W2,
                             const float* __restrict__ b2,
                             float* __restrict__ out) {
    __shared__ int   bs[N_MOL];           // 8KB
    __shared__ float ys[NGRAPH * HEADS];  // 4KB
    __shared__ int   nonmono;

    int tid = threadIdx.x;  // 0..1023
    const int* p32 = (const int*)batch_raw;

    if (tid == 0) nonmono = 0;
    __syncthreads();

    // Read first 2048 32-bit words (safe for both dtypes).
    for (int i = tid; i < N_MOL; i += 1024) bs[i] = p32[i];
    __syncthreads();
    // Sorted int32 batch ids are monotone non-decreasing; int64's interleaved
    // (value, 0) word stream is not (for any nonzero data).
    for (int i = tid; i < N_MOL - 1; i += 1024)
        if (bs[i] > bs[i + 1]) nonmono = 1;
    __syncthreads();
    if (nonmono) {  // int64: value = low word at 2*i (buffer is 4096 words)
        for (int i = tid; i < N_MOL; i += 1024) bs[i] = p32[2 * i];
        __syncthreads();
    }

    int b = tid >> 4;  // graph 0..63
    int h = tid & 15;

    // lower_bound for b and b+1 in sorted bs
    int s, e;
    {
        int lo = 0, hi = N_MOL;
        while (lo < hi) { int m = (lo + hi) >> 1; if (bs[m] < b) lo = m + 1; else hi = m; }
        s = lo;
        lo = 0; hi = N_MOL;
        while (lo < hi) { int m = (lo + hi) >> 1; if (bs[m] < b + 1) lo = m + 1; else hi = m; }
        e = lo;
    }

    float acc = 0.0f;
    for (int n = s; n < e; n++) acc += g_y_atom[n * HEADS + h];
    ys[b * HEADS + h] = acc * 0.001f;
    __syncthreads();

    if (tid < NGRAPH) {
        float o = b2[0];
#pragma unroll
        for (int j = 0; j < 2 * HEADS; j++) {
            float a = b1[j];
#pragma unroll
            for (int hh = 0; hh < HEADS; hh++)
                a += ys[tid * HEADS + hh] * W1[hh * (2 * HEADS) + j];
            float el = (a > 0.0f) ? a : (expf(a) - 1.0f);
            o += el * W2[j];
        }
        out[tid] = o;
    }
}

// ---------------------------------------------------------------------------
// Inputs (metadata order):
// 0 mol_feats [2048,64] f32   1 fused_feats [2048,64] f32
// 2 Wmu [128,16] f32          3 bmu [16] f32
// 4 W1 [16,32] f32            5 b1 [32] f32
// 6 W2 [32,1] f32             7 b2 [1] f32
// 8 mol_batch [2048] int64-or-int32   9 num_graphs (ignored; B=64 static)
// ---------------------------------------------------------------------------
extern "C" void kernel_launch(void* const* d_in, const int* in_sizes, int n_in,
                              void* d_out, int out_size) {
    const float* mol  = (const float*)d_in[0];
    const float* pro  = (const float*)d_in[1];
    const float* Wmu  = (const float*)d_in[2];
    const float* bmu  = (const float*)d_in[3];
    const float* W1   = (const float*)d_in[4];
    const float* b1   = (const float*)d_in[5];
    const float* W2   = (const float*)d_in[6];
    const float* b2   = (const float*)d_in[7];
    const void*  mb   = (const void*)d_in[8];
    float* out = (float*)d_out;

    proj_kernel<<<(N_MOL + P_PRO) / 16, 256>>>(mol, pro, Wmu, bmu);
    sort_scan_kernel<<<HEADS, 1024>>>();
    ya_kernel<<<(N_MOL * HEADS) / 1024, 1024>>>();
    final_kernel<<<1, 1024>>>(mb, W1, b1, W2, b2, out);
}

// round 2
// speedup vs baseline: 2.0240x; 2.0240x over previous
#include <cuda_runtime.h>
#include <math.h>

#define N_MOL  2048
#define P_PRO  2048
#define HID    64
#define HEADS  16
#define NGRAPH 64
#define NB     256          // counting-sort bins
#define NBLK   128          // grid size (all co-resident on 148 SMs)
#define NTHR   256

// ---- scratch (no allocation allowed) ----
__device__ float g_amolT[HEADS][N_MOL];
__device__ float g_aproT[HEADS][P_PRO];
__device__ float g_ys[NGRAPH * HEADS];
__device__ int   g_gen;     // barrier generation (monotone across replays)
__device__ int   g_count;   // barrier arrivals (returns to 0 each run)
__device__ int   g_done;    // head-blocks-finished counter (returns to 0)

struct SmemB {
    float  bufA[P_PRO];      // raw a_pro  -> later y_atom
    float  bufB[P_PRO];      // bin-sorted values
    float  bufC[P_PRO];      // bin-sorted exp(values)
    int    bs[N_MOL];        // batch ids
    int    hist[NB];
    int    cnt[NB];
    int    binStart[NB + 1];
    int    iscan[2][NB];
    float  prefExp[NB + 1];  // sum exp over bins < k
    float  sufVal[NB + 1];   // sum val over bins >= k
    double dtmp[2][NB];
    float  redmn[8], redmx[8];
    float  mnv, mxv;
    int    flag;
};
struct SmemA { float rows[16][HID]; };
union SmemU { SmemA a; SmemB b; };

__device__ __forceinline__ int bin_of(float v, float mn, float inv) {
    // no-FMA-contraction form so all call sites compute identically
    int b = (int)(__fmul_rn(__fsub_rn(v, mn), inv));
    return b < 0 ? 0 : (b > NB - 1 ? NB - 1 : b);
}

__global__ __launch_bounds__(NTHR, 1)
void fused_kernel(const float* __restrict__ mol,
                  const float* __restrict__ pro,
                  const float* __restrict__ Wmu,
                  const float* __restrict__ bmu,
                  const float* __restrict__ W1,
                  const float* __restrict__ b1,
                  const float* __restrict__ W2,
                  const float* __restrict__ b2,
                  const int*   __restrict__ batch32,
                  float* __restrict__ out) {
    __shared__ SmemU sm;
    int tid = threadIdx.x;

    // ================= Phase A: projections (all 128 blocks) =================
    // block handles 32 rows (of 4096 = mol then pro), all 16 heads.
    {
        int r16 = tid >> 4;       // 0..15
        int h   = tid & 15;
        for (int half = 0; half < 2; half++) {
            int rowbase = blockIdx.x * 32 + half * 16;
            // cooperative load: 16 rows x 64 floats, one float4 per thread
            {
                int lrow = tid >> 4, c4 = tid & 15;
                int grow = rowbase + lrow;
                const float* base = (grow < N_MOL) ? (mol + grow * HID)
                                                   : (pro + (grow - N_MOL) * HID);
                *(float4*)&sm.a.rows[lrow][c4 * 4] = *(const float4*)(base + c4 * 4);
            }
            __syncthreads();
            int grow = rowbase + r16;
            bool is_mol = (grow < N_MOL);
            float acc = is_mol ? bmu[h] : 0.0f;
            const float* w = is_mol ? (Wmu + h) : (Wmu + HID * HEADS + h);
#pragma unroll
            for (int k = 0; k < HID; k++)
                acc += sm.a.rows[r16][k] * w[k * HEADS];
            if (is_mol) g_amolT[h][grow] = acc;
            else        g_aproT[h][grow - N_MOL] = acc;
            __syncthreads();
        }
    }

    // ================= grid barrier =================
    __threadfence();
    __syncthreads();
    if (tid == 0) {
        int my = *(volatile int*)&g_gen;
        if (atomicAdd(&g_count, 1) == NBLK - 1) {
            atomicExch(&g_count, 0);
            __threadfence();
            atomicAdd(&g_gen, 1);
        } else {
            while (*(volatile int*)&g_gen == my) { __nanosleep(64); }
        }
        __threadfence();
    }
    __syncthreads();
    if (blockIdx.x >= HEADS) return;

    // ================= Phase B: per-head pipeline (blocks 0..15) =================
    int h = blockIdx.x;

    // load raw a_pro, batch ids; min/max reduce
    float mn = 1e30f, mx = -1e30f;
    for (int i = tid; i < P_PRO; i += NTHR) {
        float v = g_aproT[h][i];
        sm.b.bufA[i] = v;
        mn = fminf(mn, v); mx = fmaxf(mx, v);
    }
    for (int i = tid; i < N_MOL; i += NTHR) sm.b.bs[i] = batch32[i];
    if (tid == 0) sm.b.flag = 0;
    for (int i = tid; i < NB; i += NTHR) { sm.b.hist[i] = 0; sm.b.cnt[i] = 0; }
#pragma unroll
    for (int o = 16; o > 0; o >>= 1) {
        mn = fminf(mn, __shfl_xor_sync(0xffffffffu, mn, o));
        mx = fmaxf(mx, __shfl_xor_sync(0xffffffffu, mx, o));
    }
    if ((tid & 31) == 0) { sm.b.redmn[tid >> 5] = mn; sm.b.redmx[tid >> 5] = mx; }
    __syncthreads();
    if (tid == 0) {
        float a = sm.b.redmn[0], b = sm.b.redmx[0];
#pragma unroll
        for (int i = 1; i < NTHR / 32; i++) {
            a = fminf(a, sm.b.redmn[i]); b = fmaxf(b, sm.b.redmx[i]);
        }
        sm.b.mnv = a; sm.b.mxv = b;
    }
    // batch monotonicity check (int64 detection): int64 word stream is not monotone
    for (int i = tid; i < N_MOL - 1; i += NTHR)
        if (sm.b.bs[i] > sm.b.bs[i + 1]) sm.b.flag = 1;
    __syncthreads();
    if (sm.b.flag) {  // int64: take low word of each element
        for (int i = tid; i < N_MOL; i += NTHR) sm.b.bs[i] = batch32[2 * i];
    }
    float mnv = sm.b.mnv;
    float inv = (sm.b.mxv > mnv) ? (float)NB / (sm.b.mxv - mnv) : 0.0f;

    // histogram
    for (int i = tid; i < P_PRO; i += NTHR)
        atomicAdd(&sm.b.hist[bin_of(sm.b.bufA[i], mnv, inv)], 1);
    __syncthreads();

    // exclusive scan -> binStart
    {
        sm.b.iscan[0][tid] = sm.b.hist[tid];
        int src = 0;
        for (int off = 1; off < NB; off <<= 1) {
            __syncthreads();
            int v = sm.b.iscan[src][tid];
            if (tid >= off) v += sm.b.iscan[src][tid - off];
            sm.b.iscan[1 - src][tid] = v;
            src ^= 1;
        }
        __syncthreads();
        sm.b.binStart[tid + 1] = sm.b.iscan[src][tid];
        if (tid == 0) sm.b.binStart[0] = 0;
    }
    __syncthreads();

    // scatter into bins (value + exp)
    for (int i = tid; i < P_PRO; i += NTHR) {
        float v = sm.b.bufA[i];
        int b = bin_of(v, mnv, inv);
        int pos = sm.b.binStart[b] + atomicAdd(&sm.b.cnt[b], 1);
        sm.b.bufB[pos] = v;
        sm.b.bufC[pos] = expf(v);
    }
    __syncthreads();

    // per-bin sums (thread tid == bin tid)
    float se = 0.0f, svv = 0.0f;
    for (int i = sm.b.binStart[tid]; i < sm.b.binStart[tid + 1]; i++) {
        se += sm.b.bufC[i]; svv += sm.b.bufB[i];
    }
    // scan 1: exclusive prefix of sumExp
    {
        sm.b.dtmp[0][tid] = (double)se;
        int src = 0;
        for (int off = 1; off < NB; off <<= 1) {
            __syncthreads();
            double v = sm.b.dtmp[src][tid];
            if (tid >= off) v += sm.b.dtmp[src][tid - off];
            sm.b.dtmp[1 - src][tid] = v;
            src ^= 1;
        }
        __syncthreads();
        sm.b.prefExp[tid] = (float)(sm.b.dtmp[src][tid] - (double)se);
        __syncthreads();
    }
    // scan 2: suffix of sumVal  (sufVal[k] = sum over bins >= k)
    {
        sm.b.dtmp[0][tid] = (double)svv;
        int src = 0;
        for (int off = 1; off < NB; off <<= 1) {
            __syncthreads();
            double v = sm.b.dtmp[src][tid];
            if (tid >= off) v += sm.b.dtmp[src][tid - off];
            sm.b.dtmp[1 - src][tid] = v;
            src ^= 1;
        }
        __syncthreads();
        double total = sm.b.dtmp[src][NB - 1];
        sm.b.sufVal[tid] = (float)(total - (sm.b.dtmp[src][tid] - (double)svv));
        if (tid == 0) sm.b.sufVal[NB] = 0.0f;
    }
    __syncthreads();

    // queries: y_atom[n,h] for all n
    for (int n = tid; n < N_MOL; n += NTHR) {
        float am  = g_amolT[h][n];
        float t   = -am;
        float eam = expf(am);
        int b = (inv == 0.0f) ? 0 : bin_of(t, mnv, inv);
        int e1i = sm.b.binStart[b + 1];
        float acc = eam * sm.b.prefExp[b] + sm.b.sufVal[b + 1]
                  + (float)(P_PRO - e1i) * (am + 1.0f);
        for (int i = sm.b.binStart[b]; i < e1i; i++) {
            float v = sm.b.bufB[i];
            acc += (v <= t) ? eam * sm.b.bufC[i] : (am + 1.0f + v);
        }
        sm.b.bufA[n] = acc;   // bufA reused: raw values no longer needed
    }
    __syncthreads();

    // segment sum -> g_ys[b*HEADS+h]
    if (tid < NGRAPH) {
        int b = tid;
        int lo = 0, hi = N_MOL;
        while (lo < hi) { int m = (lo + hi) >> 1; if (sm.b.bs[m] < b) lo = m + 1; else hi = m; }
        int s = lo;
        lo = 0; hi = N_MOL;
        while (lo < hi) { int m = (lo + hi) >> 1; if (sm.b.bs[m] < b + 1) lo = m + 1; else hi = m; }
        int e = lo;
        float acc = 0.0f;
        for (int n = s; n < e; n++) acc += sm.b.bufA[n];
        g_ys[b * HEADS + h] = acc * 0.001f;
    }
    __threadfence();
    __syncthreads();
    if (tid == 0) atomicAdd(&g_done, 1);

    // ================= final MLP (block 0 after all heads done) =================
    if (blockIdx.x == 0) {
        if (tid == 0) {
            while (atomicAdd(&g_done, 0) < HEADS) { __nanosleep(64); }
            atomicExch(&g_done, 0);            // reset for next replay
            __threadfence();
        }
        __syncthreads();
        if (tid < NGRAPH) {
            float ys[HEADS];
#pragma unroll
            for (int hh = 0; hh < HEADS; hh++)
                ys[hh] = __ldcg(&g_ys[tid * HEADS + hh]);  // L1-bypass
            float o = b2[0];
#pragma unroll
            for (int j = 0; j < 2 * HEADS; j++) {
                float a = b1[j];
#pragma unroll
                for (int hh = 0; hh < HEADS; hh++)
                    a += ys[hh] * W1[hh * (2 * HEADS) + j];
                float el = (a > 0.0f) ? a : (expf(a) - 1.0f);
                o += el * W2[j];
            }
            out[tid] = o;
        }
    }
}

// Inputs (metadata order):
// 0 mol_feats [2048,64] f32   1 fused_feats [2048,64] f32
// 2 Wmu [128,16] f32          3 bmu [16] f32
// 4 W1 [16,32] f32            5 b1 [32] f32
// 6 W2 [32,1] f32             7 b2 [1] f32
// 8 mol_batch [2048] int64-or-int32   9 num_graphs (static B=64)
extern "C" void kernel_launch(void* const* d_in, const int* in_sizes, int n_in,
                              void* d_out, int out_size) {
    fused_kernel<<<NBLK, NTHR>>>(
        (const float*)d_in[0], (const float*)d_in[1],
        (const float*)d_in[2], (const float*)d_in[3],
        (const float*)d_in[4], (const float*)d_in[5],
        (const float*)d_in[6], (const float*)d_in[7],
        (const int*)d_in[8], (float*)d_out);
}